// round 8
// baseline (speedup 1.0000x reference)
#include <cuda_runtime.h>
#include <cuda_bf16.h>
#include <cstdint>

#define NNODES 50000
#define NEDGES 800000
#define NGRAPH 256
#define INC    128
#define HID    256

#define BM 128
#define BN 128
#define BK 32
#define SA 40
#define SB 136

// Packed-weight pool offsets (uint2 pairs; one pair = 2 columns hi+lo)
#define W1_0_P 0
#define W2_0_P 16384
#define W1S_P  49152
#define W2S_P  147456
#define WTOT_P 245760

static __device__ __align__(16) float g_z[(size_t)NNODES * HID];
static __device__ __align__(16) float g_h[(size_t)NNODES * HID];
static __device__ __align__(16) uint2 g_t2[(size_t)NNODES * 128];
static __device__ __align__(16) uint2 g_w2[WTOT_P];
static __device__ unsigned g_flags[2];

__device__ __forceinline__ int ld_idx(const void* p, long long i, bool is64) {
    if (is64) return (int)__ldg(&((const long long*)p)[i]);
    return __ldg(&((const int*)p)[i]);
}

__device__ __forceinline__ void cvt_hilo(float x0, float x1, unsigned& hi, unsigned& lo) {
    unsigned h;
    asm("cvt.rn.bf16x2.f32 %0, %1, %2;" : "=r"(h) : "f"(x1), "f"(x0));
    float f0 = __uint_as_float(h << 16);
    float f1 = __uint_as_float(h & 0xffff0000u);
    float r0 = x0 - f0, r1 = x1 - f1;
    unsigned l;
    asm("cvt.rn.bf16x2.f32 %0, %1, %2;" : "=r"(l) : "f"(r1), "f"(r0));
    hi = h; lo = l;
}

__global__ void k_init(float* __restrict__ out) {
    int tid = blockIdx.x * blockDim.x + threadIdx.x;
    if (tid < 2) g_flags[tid] = 0u;
    for (int i = tid; i < NGRAPH * HID; i += gridDim.x * blockDim.x) out[i] = 0.f;
}

__global__ void k_detect(const unsigned* __restrict__ ei, const unsigned* __restrict__ ba) {
    long long stride = (long long)gridDim.x * blockDim.x;
    long long tid = (long long)blockIdx.x * blockDim.x + threadIdx.x;
    unsigned acc = 0;
    for (long long w = 2 * tid + 1; w < 2LL * NEDGES; w += 2 * stride) acc |= ei[w];
    if (acc) atomicOr(&g_flags[0], 1u);
    acc = 0;
    for (long long w = 2 * tid + 1; w < NNODES; w += 2 * stride) acc |= ba[w];
    if (acc) atomicOr(&g_flags[1], 1u);
}

// All weights -> packed bf16 hi/lo pool in ONE launch
__global__ void k_cvt_all(const float* __restrict__ w1_0, const float* __restrict__ w2_0,
                          const float* __restrict__ w1s, const float* __restrict__ w2s) {
    int stride = gridDim.x * blockDim.x;
    for (int j = blockIdx.x * blockDim.x + threadIdx.x; j < WTOT_P; j += stride) {
        const float* src;
        int off;
        if (j < W2_0_P)      { src = w1_0; off = j - W1_0_P; }
        else if (j < W1S_P)  { src = w2_0; off = j - W2_0_P; }
        else if (j < W2S_P)  { src = w1s;  off = j - W1S_P; }
        else                 { src = w2s;  off = j - W2S_P; }
        float2 v = *(const float2*)(src + 2 * off);
        unsigned hp, lp;
        cvt_hilo(v.x, v.y, hp, lp);
        g_w2[j] = make_uint2(hp, lp);
    }
}

__global__ void k_copy4(const float4* __restrict__ src, float4* __restrict__ dst, long long n4) {
    long long stride = (long long)gridDim.x * blockDim.x;
    for (long long i = (long long)blockIdx.x * blockDim.x + threadIdx.x; i < n4; i += stride)
        dst[i] = src[i];
}

// Warp-per-edge scatter: lanes 0/1 load (src,dst) once, shfl-broadcast,
// each lane handles ngroups/32 float4 column-groups.
__global__ void k_scatter(const float* __restrict__ h, float* __restrict__ z,
                          const void* __restrict__ ei, int ngroups) {
    bool is64 = (g_flags[0] == 0u);
    int lane = threadIdx.x & 31;
    long long warp = ((long long)blockIdx.x * blockDim.x + threadIdx.x) >> 5;
    long long nwarps = ((long long)gridDim.x * blockDim.x) >> 5;
    int hc = ngroups * 4;
    for (long long e = warp; e < NEDGES; e += nwarps) {
        int idxv = 0;
        if (lane < 2) idxv = ld_idx(ei, lane == 0 ? e : NEDGES + e, is64);
        int s = __shfl_sync(0xffffffffu, idxv, 0);
        int d = __shfl_sync(0xffffffffu, idxv, 1);
        const float4* hs = (const float4*)(h + (long long)s * hc);
        float* zd = z + (long long)d * hc;
#pragma unroll 2
        for (int g = lane; g < ngroups; g += 32) {
            float4 v = hs[g];
            asm volatile("red.global.add.v4.f32 [%0], {%1,%2,%3,%4};"
                         :: "l"(zd + g * 4), "f"(v.x), "f"(v.y), "f"(v.z), "f"(v.w) : "memory");
        }
    }
}

// ---- shared GEMM core pieces ----
#define GEMM_PROLOG                                                                  \
    const int M = NNODES;                                                            \
    int tid = threadIdx.x;                                                           \
    int lane = tid & 31, warp = tid >> 5;                                            \
    int wm = (warp & 1) * 64, wn = (warp >> 1) * 32;                                 \
    int row0 = blockIdx.x * BM, col0 = blockIdx.y * BN;                              \
    float c[4][4][4];                                                                \
    _Pragma("unroll") for (int mt = 0; mt < 4; mt++)                                 \
        _Pragma("unroll") for (int nt = 0; nt < 4; nt++)                             \
            _Pragma("unroll") for (int i = 0; i < 4; i++) c[mt][nt][i] = 0.f;

#define STAGE_B_PACKED(W2, KT)                                                       \
    _Pragma("unroll") for (int i = 0; i < 4; i++) {                                  \
        int lin = tid + i * 256;                                                     \
        int r = lin >> 5, q = lin & 31;                                              \
        uint4 v = *(const uint4*)(W2 + ((KT) + r) * 128 + (col0 >> 1) + q * 2);      \
        *(uint2*)&Bh[r * SB + q * 4] = make_uint2(v.x, v.z);                         \
        *(uint2*)&Bl[r * SB + q * 4] = make_uint2(v.y, v.w);                         \
    }

#define GEMM_COMPUTE                                                                 \
    _Pragma("unroll") for (int kc = 0; kc < 2; kc++) {                               \
        unsigned ah[4][4], al[4][4], bh[4][2], bl[4][2];                             \
        int arow = lane & 15;                                                        \
        int acol = kc * 16 + (lane >> 4) * 8;                                        \
        _Pragma("unroll") for (int mt = 0; mt < 4; mt++) {                           \
            unsigned sa = (unsigned)__cvta_generic_to_shared(                        \
                &Ah[(wm + mt * 16 + arow) * SA + acol]);                             \
            asm volatile("ldmatrix.sync.aligned.m8n8.x4.shared.b16 {%0,%1,%2,%3}, [%4];" \
                         : "=r"(ah[mt][0]), "=r"(ah[mt][1]), "=r"(ah[mt][2]), "=r"(ah[mt][3]) \
                         : "r"(sa));                                                 \
            unsigned sb = (unsigned)__cvta_generic_to_shared(                        \
                &Al[(wm + mt * 16 + arow) * SA + acol]);                             \
            asm volatile("ldmatrix.sync.aligned.m8n8.x4.shared.b16 {%0,%1,%2,%3}, [%4];" \
                         : "=r"(al[mt][0]), "=r"(al[mt][1]), "=r"(al[mt][2]), "=r"(al[mt][3]) \
                         : "r"(sb));                                                 \
        }                                                                            \
        int brow = kc * 16 + (lane & 15);                                            \
        _Pragma("unroll") for (int nt2 = 0; nt2 < 2; nt2++) {                        \
            int bcol = wn + nt2 * 16 + (lane >> 4) * 8;                              \
            unsigned sh = (unsigned)__cvta_generic_to_shared(&Bh[brow * SB + bcol]); \
            asm volatile("ldmatrix.sync.aligned.m8n8.x4.trans.shared.b16 {%0,%1,%2,%3}, [%4];" \
                         : "=r"(bh[2 * nt2][0]), "=r"(bh[2 * nt2][1]),               \
                           "=r"(bh[2 * nt2 + 1][0]), "=r"(bh[2 * nt2 + 1][1])        \
                         : "r"(sh));                                                 \
            unsigned sl = (unsigned)__cvta_generic_to_shared(&Bl[brow * SB + bcol]); \
            asm volatile("ldmatrix.sync.aligned.m8n8.x4.trans.shared.b16 {%0,%1,%2,%3}, [%4];" \
                         : "=r"(bl[2 * nt2][0]), "=r"(bl[2 * nt2][1]),               \
                           "=r"(bl[2 * nt2 + 1][0]), "=r"(bl[2 * nt2 + 1][1])        \
                         : "r"(sl));                                                 \
        }                                                                            \
        _Pragma("unroll") for (int mt = 0; mt < 4; mt++)                             \
            _Pragma("unroll") for (int nt = 0; nt < 4; nt++) {                       \
                float* cc = c[mt][nt];                                               \
                MMA3(ah[mt], al[mt], bh[nt], bl[nt], cc);                            \
            }                                                                        \
    }

#define MMA1(AREG, BREG, cc)                                                         \
    asm volatile("mma.sync.aligned.m16n8k16.row.col.f32.bf16.bf16.f32 "              \
                 "{%0,%1,%2,%3}, {%4,%5,%6,%7}, {%8,%9}, {%0,%1,%2,%3};"             \
                 : "+f"(cc[0]), "+f"(cc[1]), "+f"(cc[2]), "+f"(cc[3])                \
                 : "r"(AREG[0]), "r"(AREG[1]), "r"(AREG[2]), "r"(AREG[3]),           \
                   "r"(BREG[0]), "r"(BREG[1]))
#define MMA3(AH, AL, BH, BL, cc)                                                     \
    MMA1(AH, BH, cc); MMA1(AH, BL, cc); MMA1(AL, BH, cc)

// GEMM1: t2 = pack_hilo(relu(A32 @ W + bias))
__global__ void __launch_bounds__(256, 2)
k_gemm1(const float* __restrict__ A32, const uint2* __restrict__ W2,
        const float* __restrict__ bias, uint2* __restrict__ T2, int K) {
    __shared__ __align__(16) unsigned short Ah[BM * SA];
    __shared__ __align__(16) unsigned short Al[BM * SA];
    __shared__ __align__(16) unsigned short Bh[BK * SB];
    __shared__ __align__(16) unsigned short Bl[BK * SB];
    GEMM_PROLOG
    for (int kt = 0; kt < K; kt += BK) {
#pragma unroll
        for (int i = 0; i < 4; i++) {
            int lin = tid + i * 256;
            int r = lin >> 3, q = lin & 7;
            int gr = row0 + r;
            float4 v = make_float4(0.f, 0.f, 0.f, 0.f);
            if (gr < M) v = *(const float4*)(A32 + (long long)gr * K + kt + q * 4);
            unsigned h0, l0, h1, l1;
            cvt_hilo(v.x, v.y, h0, l0);
            cvt_hilo(v.z, v.w, h1, l1);
            *(uint2*)&Ah[r * SA + q * 4] = make_uint2(h0, h1);
            *(uint2*)&Al[r * SA + q * 4] = make_uint2(l0, l1);
        }
        STAGE_B_PACKED(W2, kt)
        __syncthreads();
        GEMM_COMPUTE
        __syncthreads();
    }
    int g = lane >> 2, tg = lane & 3;
#pragma unroll
    for (int nt = 0; nt < 4; nt++) {
        int gcol = col0 + wn + nt * 8 + tg * 2;
        float b0 = bias[gcol], b1 = bias[gcol + 1];
#pragma unroll
        for (int mt = 0; mt < 4; mt++) {
#pragma unroll
            for (int half = 0; half < 2; half++) {
                int rr = row0 + wm + mt * 16 + g + half * 8;
                if (rr < M) {
                    float ox = fmaxf(c[mt][nt][half * 2 + 0] + b0, 0.f);
                    float oy = fmaxf(c[mt][nt][half * 2 + 1] + b1, 0.f);
                    unsigned hp, lp;
                    cvt_hilo(ox, oy, hp, lp);
                    T2[(long long)rr * 128 + (gcol >> 1)] = make_uint2(hp, lp);
                }
            }
        }
    }
}

// GEMM2: r = relu(T2 @ W + bias). If pool_out: red.add r into pool_out[batch[row]]
// (and skip C). Else store C (+C2).
__global__ void __launch_bounds__(256, 2)
k_gemm2(const uint2* __restrict__ T2, const uint2* __restrict__ W2,
        const float* __restrict__ bias, float* __restrict__ C,
        float* __restrict__ C2, float* __restrict__ pool_out,
        const void* __restrict__ ba, int K) {
    __shared__ __align__(16) unsigned short Ah[BM * SA];
    __shared__ __align__(16) unsigned short Al[BM * SA];
    __shared__ __align__(16) unsigned short Bh[BK * SB];
    __shared__ __align__(16) unsigned short Bl[BK * SB];
    GEMM_PROLOG
    for (int kt = 0; kt < K; kt += BK) {
#pragma unroll
        for (int i = 0; i < 4; i++) {
            int lin = tid + i * 256;
            int r = lin >> 3, q = lin & 7;
            int gr = row0 + r;
            uint4 v = make_uint4(0u, 0u, 0u, 0u);
            if (gr < M) v = *(const uint4*)(T2 + (long long)gr * 128 + ((kt + q * 4) >> 1));
            *(uint2*)&Ah[r * SA + q * 4] = make_uint2(v.x, v.z);
            *(uint2*)&Al[r * SA + q * 4] = make_uint2(v.y, v.w);
        }
        STAGE_B_PACKED(W2, kt)
        __syncthreads();
        GEMM_COMPUTE
        __syncthreads();
    }
    bool is64b = (g_flags[1] == 0u);
    int g = lane >> 2, tg = lane & 3;
#pragma unroll
    for (int nt = 0; nt < 4; nt++) {
        int gcol = col0 + wn + nt * 8 + tg * 2;
        float b0 = bias[gcol], b1 = bias[gcol + 1];
#pragma unroll
        for (int mt = 0; mt < 4; mt++) {
#pragma unroll
            for (int half = 0; half < 2; half++) {
                int rr = row0 + wm + mt * 16 + g + half * 8;
                if (rr < M) {
                    float2 o;
                    o.x = fmaxf(c[mt][nt][half * 2 + 0] + b0, 0.f);
                    o.y = fmaxf(c[mt][nt][half * 2 + 1] + b1, 0.f);
                    if (pool_out) {
                        int gb = ld_idx(ba, rr, is64b);
                        float* dp = pool_out + (long long)gb * HID + gcol;
                        asm volatile("red.global.add.v2.f32 [%0], {%1,%2};"
                                     :: "l"(dp), "f"(o.x), "f"(o.y) : "memory");
                    } else {
                        long long off = (long long)rr * HID + gcol;
                        *(float2*)(C + off) = o;
                        if (C2) *(float2*)(C2 + off) = o;
                    }
                }
            }
        }
    }
}

extern "C" void kernel_launch(void* const* d_in, const int* in_sizes, int n_in,
                              void* d_out, int out_size) {
    const float* x    = (const float*)d_in[0];
    const void*  ei   = d_in[1];
    const void*  ba   = d_in[2];
    const float* w1_0 = (const float*)d_in[3];
    const float* b1_0 = (const float*)d_in[4];
    const float* w2_0 = (const float*)d_in[5];
    const float* b2_0 = (const float*)d_in[6];
    const float* w1s  = (const float*)d_in[7];
    const float* b1s  = (const float*)d_in[8];
    const float* w2s  = (const float*)d_in[9];
    const float* b2s  = (const float*)d_in[10];
    float* out = (float*)d_out;

    float *z, *h;
    uint2 *t2, *w2;
    cudaGetSymbolAddress((void**)&z, g_z);
    cudaGetSymbolAddress((void**)&h, g_h);
    cudaGetSymbolAddress((void**)&t2, g_t2);
    cudaGetSymbolAddress((void**)&w2, g_w2);

    dim3 ggrid((NNODES + BM - 1) / BM, HID / BN);  // (391, 2)

    // Launch order matters for ncu (-s 5 -c 1): #5 must be k_gemm1.
    k_init<<<64, 256>>>(out);                                       // 0
    k_detect<<<256, 256>>>((const unsigned*)ei, (const unsigned*)ba); // 1
    k_cvt_all<<<480, 256>>>(w1_0, w2_0, w1s, w2s);                  // 2
    k_copy4<<<2048, 256>>>((const float4*)x, (float4*)z,            // 3
                           (long long)NNODES * INC / 4);
    k_scatter<<<3552, 256>>>(x, z, ei, INC / 4);                    // 4
    k_gemm1<<<ggrid, 256>>>(z, w2 + W1_0_P, b1_0, t2, INC);         // 5 <- profiled
    k_gemm2<<<ggrid, 256>>>(t2, w2 + W2_0_P, b2_0, h, z, nullptr, nullptr, HID);

    for (int l = 0; l < 3; l++) {
        k_scatter<<<3552, 256>>>(h, z, ei, HID / 4);
        k_gemm1<<<ggrid, 256>>>(z, w2 + W1S_P + l * (HID * HID / 2), b1s + l * HID, t2, HID);
        if (l < 2) {
            k_gemm2<<<ggrid, 256>>>(t2, w2 + W2S_P + l * (HID * HID / 2), b2s + l * HID,
                                    h, z, nullptr, nullptr, HID);
        } else {
            // Final layer: fuse global_add_pool into the epilogue; h never materialized.
            k_gemm2<<<ggrid, 256>>>(t2, w2 + W2S_P + l * (HID * HID / 2), b2s + l * HID,
                                    nullptr, nullptr, out, ba, HID);
        }
    }
}

// round 9
// speedup vs baseline: 1.0307x; 1.0307x over previous
#include <cuda_runtime.h>
#include <cuda_bf16.h>
#include <cstdint>

#define NNODES 50000
#define NEDGES 800000
#define NGRAPH 256
#define INC    128
#define HID    256

#define BM 128
#define BN 128
#define BK 32
#define SA 40
#define SB 136

// Packed-weight pool offsets (uint2 pairs; one pair = 2 columns hi+lo)
#define W1_0_P 0
#define W2_0_P 16384
#define W1S_P  49152
#define W2S_P  147456
#define WTOT_P 245760

static __device__ __align__(16) float g_z[(size_t)NNODES * HID];
static __device__ __align__(16) float g_h[(size_t)NNODES * HID];
static __device__ __align__(16) uint2 g_t2[(size_t)NNODES * 128];
static __device__ __align__(16) uint2 g_w2[WTOT_P];
static __device__ unsigned g_flags[2];

__device__ __forceinline__ int ld_idx(const void* p, long long i, bool is64) {
    if (is64) return (int)__ldg(&((const long long*)p)[i]);
    return __ldg(&((const int*)p)[i]);
}

__device__ __forceinline__ void cvt_hilo(float x0, float x1, unsigned& hi, unsigned& lo) {
    unsigned h;
    asm("cvt.rn.bf16x2.f32 %0, %1, %2;" : "=r"(h) : "f"(x1), "f"(x0));
    float f0 = __uint_as_float(h << 16);
    float f1 = __uint_as_float(h & 0xffff0000u);
    float r0 = x0 - f0, r1 = x1 - f1;
    unsigned l;
    asm("cvt.rn.bf16x2.f32 %0, %1, %2;" : "=r"(l) : "f"(r1), "f"(r0));
    hi = h; lo = l;
}

// Launch 0: zero out+flags AND copy x -> z (fused to compact launch count)
__global__ void k_init_copy(float* __restrict__ out, const float4* __restrict__ x,
                            float4* __restrict__ z) {
    long long tid = (long long)blockIdx.x * blockDim.x + threadIdx.x;
    long long stride = (long long)gridDim.x * blockDim.x;
    if (tid < 2) g_flags[tid] = 0u;
    for (long long i = tid; i < NGRAPH * HID; i += stride) out[i] = 0.f;
    const long long n4 = (long long)NNODES * INC / 4;
    for (long long i = tid; i < n4; i += stride) z[i] = x[i];
}

// Launch 1: dtype detect AND weight pre-convert (fused)
__global__ void k_detect_cvt(const unsigned* __restrict__ ei, const unsigned* __restrict__ ba,
                             const float* __restrict__ w1_0, const float* __restrict__ w2_0,
                             const float* __restrict__ w1s, const float* __restrict__ w2s) {
    long long stride = (long long)gridDim.x * blockDim.x;
    long long tid = (long long)blockIdx.x * blockDim.x + threadIdx.x;
    // weight conversion
    for (long long j = tid; j < WTOT_P; j += stride) {
        const float* src;
        long long off;
        if (j < W2_0_P)      { src = w1_0; off = j - W1_0_P; }
        else if (j < W1S_P)  { src = w2_0; off = j - W2_0_P; }
        else if (j < W2S_P)  { src = w1s;  off = j - W1S_P; }
        else                 { src = w2s;  off = j - W2S_P; }
        float2 v = *(const float2*)(src + 2 * off);
        unsigned hp, lp;
        cvt_hilo(v.x, v.y, hp, lp);
        g_w2[j] = make_uint2(hp, lp);
    }
    // dtype detect
    unsigned acc = 0;
    for (long long w = 2 * tid + 1; w < 2LL * NEDGES; w += 2 * stride) acc |= ei[w];
    if (acc) atomicOr(&g_flags[0], 1u);
    acc = 0;
    for (long long w = 2 * tid + 1; w < NNODES; w += 2 * stride) acc |= ba[w];
    if (acc) atomicOr(&g_flags[1], 1u);
}

// Thread-per-(edge, float4-group) scatter (R7-proven form)
__global__ void k_scatter(const float* __restrict__ h, float* __restrict__ z,
                          const void* __restrict__ ei, int lg) {
    bool is64 = (g_flags[0] == 0u);
    long long total = (long long)NEDGES << lg;
    long long stride = (long long)gridDim.x * blockDim.x;
    long long mask = (1LL << lg) - 1;
    for (long long t = (long long)blockIdx.x * blockDim.x + threadIdx.x; t < total; t += stride) {
        long long e = t >> lg;
        int c = (int)(t & mask) * 4;
        int s = ld_idx(ei, e, is64);
        int d = ld_idx(ei, (long long)NEDGES + e, is64);
        const float4 v = *(const float4*)(h + ((long long)s << (lg + 2)) + c);
        float* dp = z + ((long long)d << (lg + 2)) + c;
        asm volatile("red.global.add.v4.f32 [%0], {%1,%2,%3,%4};"
                     :: "l"(dp), "f"(v.x), "f"(v.y), "f"(v.z), "f"(v.w) : "memory");
    }
}

// ---- shared GEMM core pieces ----
#define GEMM_PROLOG                                                                  \
    const int M = NNODES;                                                            \
    int tid = threadIdx.x;                                                           \
    int lane = tid & 31, warp = tid >> 5;                                            \
    int wm = (warp & 1) * 64, wn = (warp >> 1) * 32;                                 \
    int row0 = blockIdx.x * BM, col0 = blockIdx.y * BN;                              \
    float c[4][4][4];                                                                \
    _Pragma("unroll") for (int mt = 0; mt < 4; mt++)                                 \
        _Pragma("unroll") for (int nt = 0; nt < 4; nt++)                             \
            _Pragma("unroll") for (int i = 0; i < 4; i++) c[mt][nt][i] = 0.f;

#define STAGE_B_PACKED(W2, KT)                                                       \
    _Pragma("unroll") for (int i = 0; i < 4; i++) {                                  \
        int lin = tid + i * 256;                                                     \
        int r = lin >> 5, q = lin & 31;                                              \
        uint4 v = *(const uint4*)(W2 + ((KT) + r) * 128 + (col0 >> 1) + q * 2);      \
        *(uint2*)&Bh[r * SB + q * 4] = make_uint2(v.x, v.z);                         \
        *(uint2*)&Bl[r * SB + q * 4] = make_uint2(v.y, v.w);                         \
    }

#define GEMM_COMPUTE                                                                 \
    _Pragma("unroll") for (int kc = 0; kc < 2; kc++) {                               \
        unsigned ah[4][4], al[4][4], bh[4][2], bl[4][2];                             \
        int arow = lane & 15;                                                        \
        int acol = kc * 16 + (lane >> 4) * 8;                                        \
        _Pragma("unroll") for (int mt = 0; mt < 4; mt++) {                           \
            unsigned sa = (unsigned)__cvta_generic_to_shared(                        \
                &Ah[(wm + mt * 16 + arow) * SA + acol]);                             \
            asm volatile("ldmatrix.sync.aligned.m8n8.x4.shared.b16 {%0,%1,%2,%3}, [%4];" \
                         : "=r"(ah[mt][0]), "=r"(ah[mt][1]), "=r"(ah[mt][2]), "=r"(ah[mt][3]) \
                         : "r"(sa));                                                 \
            unsigned sb = (unsigned)__cvta_generic_to_shared(                        \
                &Al[(wm + mt * 16 + arow) * SA + acol]);                             \
            asm volatile("ldmatrix.sync.aligned.m8n8.x4.shared.b16 {%0,%1,%2,%3}, [%4];" \
                         : "=r"(al[mt][0]), "=r"(al[mt][1]), "=r"(al[mt][2]), "=r"(al[mt][3]) \
                         : "r"(sb));                                                 \
        }                                                                            \
        int brow = kc * 16 + (lane & 15);                                            \
        _Pragma("unroll") for (int nt2 = 0; nt2 < 2; nt2++) {                        \
            int bcol = wn + nt2 * 16 + (lane >> 4) * 8;                              \
            unsigned sh = (unsigned)__cvta_generic_to_shared(&Bh[brow * SB + bcol]); \
            asm volatile("ldmatrix.sync.aligned.m8n8.x4.trans.shared.b16 {%0,%1,%2,%3}, [%4];" \
                         : "=r"(bh[2 * nt2][0]), "=r"(bh[2 * nt2][1]),               \
                           "=r"(bh[2 * nt2 + 1][0]), "=r"(bh[2 * nt2 + 1][1])        \
                         : "r"(sh));                                                 \
            unsigned sl = (unsigned)__cvta_generic_to_shared(&Bl[brow * SB + bcol]); \
            asm volatile("ldmatrix.sync.aligned.m8n8.x4.trans.shared.b16 {%0,%1,%2,%3}, [%4];" \
                         : "=r"(bl[2 * nt2][0]), "=r"(bl[2 * nt2][1]),               \
                           "=r"(bl[2 * nt2 + 1][0]), "=r"(bl[2 * nt2 + 1][1])        \
                         : "r"(sl));                                                 \
        }                                                                            \
        _Pragma("unroll") for (int mt = 0; mt < 4; mt++)                             \
            _Pragma("unroll") for (int nt = 0; nt < 4; nt++) {                       \
                float* cc = c[mt][nt];                                               \
                MMA3(ah[mt], al[mt], bh[nt], bl[nt], cc);                            \
            }                                                                        \
    }

#define MMA1(AREG, BREG, cc)                                                         \
    asm volatile("mma.sync.aligned.m16n8k16.row.col.f32.bf16.bf16.f32 "              \
                 "{%0,%1,%2,%3}, {%4,%5,%6,%7}, {%8,%9}, {%0,%1,%2,%3};"             \
                 : "+f"(cc[0]), "+f"(cc[1]), "+f"(cc[2]), "+f"(cc[3])                \
                 : "r"(AREG[0]), "r"(AREG[1]), "r"(AREG[2]), "r"(AREG[3]),           \
                   "r"(BREG[0]), "r"(BREG[1]))
#define MMA3(AH, AL, BH, BL, cc)                                                     \
    MMA1(AH, BH, cc); MMA1(AH, BL, cc); MMA1(AL, BH, cc)

// GEMM1: t2 = pack_hilo(relu(A32 @ W + bias))
__global__ void __launch_bounds__(256, 2)
k_gemm1(const float* __restrict__ A32, const uint2* __restrict__ W2,
        const float* __restrict__ bias, uint2* __restrict__ T2, int K) {
    __shared__ __align__(16) unsigned short Ah[BM * SA];
    __shared__ __align__(16) unsigned short Al[BM * SA];
    __shared__ __align__(16) unsigned short Bh[BK * SB];
    __shared__ __align__(16) unsigned short Bl[BK * SB];
    GEMM_PROLOG
    for (int kt = 0; kt < K; kt += BK) {
#pragma unroll
        for (int i = 0; i < 4; i++) {
            int lin = tid + i * 256;
            int r = lin >> 3, q = lin & 7;
            int gr = row0 + r;
            float4 v = make_float4(0.f, 0.f, 0.f, 0.f);
            if (gr < M) v = *(const float4*)(A32 + (long long)gr * K + kt + q * 4);
            unsigned h0, l0, h1, l1;
            cvt_hilo(v.x, v.y, h0, l0);
            cvt_hilo(v.z, v.w, h1, l1);
            *(uint2*)&Ah[r * SA + q * 4] = make_uint2(h0, h1);
            *(uint2*)&Al[r * SA + q * 4] = make_uint2(l0, l1);
        }
        STAGE_B_PACKED(W2, kt)
        __syncthreads();
        GEMM_COMPUTE
        __syncthreads();
    }
    int g = lane >> 2, tg = lane & 3;
#pragma unroll
    for (int nt = 0; nt < 4; nt++) {
        int gcol = col0 + wn + nt * 8 + tg * 2;
        float b0 = bias[gcol], b1 = bias[gcol + 1];
#pragma unroll
        for (int mt = 0; mt < 4; mt++) {
#pragma unroll
            for (int half = 0; half < 2; half++) {
                int rr = row0 + wm + mt * 16 + g + half * 8;
                if (rr < M) {
                    float ox = fmaxf(c[mt][nt][half * 2 + 0] + b0, 0.f);
                    float oy = fmaxf(c[mt][nt][half * 2 + 1] + b1, 0.f);
                    unsigned hp, lp;
                    cvt_hilo(ox, oy, hp, lp);
                    T2[(long long)rr * 128 + (gcol >> 1)] = make_uint2(hp, lp);
                }
            }
        }
    }
}

// GEMM2: r = relu(T2 @ W + bias). If pool_out: red.add into pool_out[batch[row]].
// Else store C (+C2).
__global__ void __launch_bounds__(256, 2)
k_gemm2(const uint2* __restrict__ T2, const uint2* __restrict__ W2,
        const float* __restrict__ bias, float* __restrict__ C,
        float* __restrict__ C2, float* __restrict__ pool_out,
        const void* __restrict__ ba, int K) {
    __shared__ __align__(16) unsigned short Ah[BM * SA];
    __shared__ __align__(16) unsigned short Al[BM * SA];
    __shared__ __align__(16) unsigned short Bh[BK * SB];
    __shared__ __align__(16) unsigned short Bl[BK * SB];
    GEMM_PROLOG
    for (int kt = 0; kt < K; kt += BK) {
#pragma unroll
        for (int i = 0; i < 4; i++) {
            int lin = tid + i * 256;
            int r = lin >> 3, q = lin & 7;
            int gr = row0 + r;
            uint4 v = make_uint4(0u, 0u, 0u, 0u);
            if (gr < M) v = *(const uint4*)(T2 + (long long)gr * 128 + ((kt + q * 4) >> 1));
            *(uint2*)&Ah[r * SA + q * 4] = make_uint2(v.x, v.z);
            *(uint2*)&Al[r * SA + q * 4] = make_uint2(v.y, v.w);
        }
        STAGE_B_PACKED(W2, kt)
        __syncthreads();
        GEMM_COMPUTE
        __syncthreads();
    }
    bool is64b = (g_flags[1] == 0u);
    int g = lane >> 2, tg = lane & 3;
#pragma unroll
    for (int nt = 0; nt < 4; nt++) {
        int gcol = col0 + wn + nt * 8 + tg * 2;
        float b0 = bias[gcol], b1 = bias[gcol + 1];
#pragma unroll
        for (int mt = 0; mt < 4; mt++) {
#pragma unroll
            for (int half = 0; half < 2; half++) {
                int rr = row0 + wm + mt * 16 + g + half * 8;
                if (rr < M) {
                    float2 o;
                    o.x = fmaxf(c[mt][nt][half * 2 + 0] + b0, 0.f);
                    o.y = fmaxf(c[mt][nt][half * 2 + 1] + b1, 0.f);
                    if (pool_out) {
                        int gb = ld_idx(ba, rr, is64b);
                        float* dp = pool_out + (long long)gb * HID + gcol;
                        asm volatile("red.global.add.v2.f32 [%0], {%1,%2};"
                                     :: "l"(dp), "f"(o.x), "f"(o.y) : "memory");
                    } else {
                        long long off = (long long)rr * HID + gcol;
                        *(float2*)(C + off) = o;
                        if (C2) *(float2*)(C2 + off) = o;
                    }
                }
            }
        }
    }
}

extern "C" void kernel_launch(void* const* d_in, const int* in_sizes, int n_in,
                              void* d_out, int out_size) {
    const float* x    = (const float*)d_in[0];
    const void*  ei   = d_in[1];
    const void*  ba   = d_in[2];
    const float* w1_0 = (const float*)d_in[3];
    const float* b1_0 = (const float*)d_in[4];
    const float* w2_0 = (const float*)d_in[5];
    const float* b2_0 = (const float*)d_in[6];
    const float* w1s  = (const float*)d_in[7];
    const float* b1s  = (const float*)d_in[8];
    const float* w2s  = (const float*)d_in[9];
    const float* b2s  = (const float*)d_in[10];
    float* out = (float*)d_out;

    float *z, *h;
    uint2 *t2, *w2;
    cudaGetSymbolAddress((void**)&z, g_z);
    cudaGetSymbolAddress((void**)&h, g_h);
    cudaGetSymbolAddress((void**)&t2, g_t2);
    cudaGetSymbolAddress((void**)&w2, g_w2);

    dim3 ggrid((NNODES + BM - 1) / BM, HID / BN);  // (391, 2)

    // ncu captures launch index 3 -> k_gemm1 (layer 0).
    k_init_copy<<<2048, 256>>>(out, (const float4*)x, (float4*)z);            // 0
    k_detect_cvt<<<960, 256>>>((const unsigned*)ei, (const unsigned*)ba,      // 1
                               w1_0, w2_0, w1s, w2s);
    k_scatter<<<4736, 256>>>(x, z, ei, 5);                                    // 2
    k_gemm1<<<ggrid, 256>>>(z, w2 + W1_0_P, b1_0, t2, INC);                   // 3 <- profiled
    k_gemm2<<<ggrid, 256>>>(t2, w2 + W2_0_P, b2_0, h, z, nullptr, nullptr, HID);

    for (int l = 0; l < 3; l++) {
        k_scatter<<<4736, 256>>>(h, z, ei, 6);
        k_gemm1<<<ggrid, 256>>>(z, w2 + W1S_P + l * (HID * HID / 2), b1s + l * HID, t2, HID);
        if (l < 2) {
            k_gemm2<<<ggrid, 256>>>(t2, w2 + W2S_P + l * (HID * HID / 2), b2s + l * HID,
                                    h, z, nullptr, nullptr, HID);
        } else {
            k_gemm2<<<ggrid, 256>>>(t2, w2 + W2S_P + l * (HID * HID / 2), b2s + l * HID,
                                    nullptr, nullptr, out, ba, HID);
        }
    }
}